// round 8
// baseline (speedup 1.0000x reference)
#include <cuda_runtime.h>
#include <cuda_bf16.h>
#include <math.h>

#define Bb   4
#define Ss   1024
#define EMB  128
#define Hh   4
#define Dd   32
#define Tt   (Ss-1)          // 1023
#define NROW (Bb*Ss)         // 4096
#define NSPL 4               // i-dimension split factor for kC
#define SCALE 0.17677669529663687f   // 1/sqrt(32)

// ---------------- scratch (static device allocations only) ----------------
__device__ float g_e   [NROW*EMB];
__device__ float g_Q   [NROW*EMB];
__device__ float g_K   [NROW*EMB];
__device__ float g_V   [NROW*EMB];
__device__ float g_sr  [NROW*Hh];
__device__ float g_EpEx[NROW*Hh];   // exclusive cumsum of ex, per (b,s,h)
__device__ float g_PpEx[NROW];      // exclusive cumsum of g, per (b,s)
__device__ float g_theta[Hh];
__device__ float g_ansc[2*EMB];     // ans_emb@Wh_bot + bh
__device__ float g_pacc [NSPL*NROW*EMB];   // unnormalized partial ctx
__device__ float g_plsum[NSPL*NROW*Hh];    // partial softmax denominators

// ---------------- kernel P: tiny precompute (parallel GEMV) ----------------
__global__ __launch_bounds__(1024) void kP(
    const float* __restrict__ ans_emb, const float* __restrict__ Wh,
    const float* __restrict__ bh, const float* __restrict__ traw)
{
    int tid  = threadIdx.x;      // 0..1023
    int o    = tid >> 2;         // output index 0..255  (f*128 + c)
    int part = tid & 3;          // k-segment
    int f = o >> 7, c = o & 127;
    float acc = 0.f;
    int k0 = part * 32;
    #pragma unroll 8
    for (int k = k0; k < k0 + 32; k++)
        acc = fmaf(ans_emb[f*128 + k], Wh[(128 + k)*128 + c], acc);
    acc += __shfl_xor_sync(0xffffffffu, acc, 1);
    acc += __shfl_xor_sync(0xffffffffu, acc, 2);
    if (part == 0) g_ansc[o] = acc + bh[c];
    if (tid < Hh) {
        float x = traw[tid];
        g_theta[tid] = log1pf(expf(x)) + 1e-4f;   // softplus + eps
    }
}

// ---------------- shared-mem GEMM helper: 16 rows x 128 cols ----------------
template<int KG>   // KG = K/4
__device__ __forceinline__ void gemmT(const float* Esh, const float* __restrict__ W,
                                      int c, float acc[16])
{
    const float4* e4 = reinterpret_cast<const float4*>(Esh);
    #pragma unroll 4
    for (int k4 = 0; k4 < KG; k4++) {
        const float* wp = W + (k4*4)*128 + c;
        float w0 = wp[0], w1 = wp[128], w2 = wp[256], w3 = wp[384];
        #pragma unroll
        for (int r = 0; r < 16; r++) {
            float4 ev = e4[r*KG + k4];
            acc[r] = fmaf(ev.x, w0, acc[r]);
            acc[r] = fmaf(ev.y, w1, acc[r]);
            acc[r] = fmaf(ev.z, w2, acc[r]);
            acc[r] = fmaf(ev.w, w3, acc[r]);
        }
    }
}

// ---------------- kernel A: gather + Q/K/inter/V + sr (32 rows/block) ------
__global__ __launch_bounds__(256) void kA(
    const int* __restrict__ idx, const int* __restrict__ flg,
    const float* __restrict__ item_emb,
    const float* __restrict__ Wq, const float* __restrict__ bq,
    const float* __restrict__ Wk, const float* __restrict__ bk,
    const float* __restrict__ Wv, const float* __restrict__ bv,
    const float* __restrict__ Wh)
{
    __shared__ __align__(16) float e_sh[32*128];   // 16KB
    __shared__ __align__(16) float q_sh[32*128];   // 16KB (later reused for inter)
    __shared__ __align__(16) float k_sh[32*128];   // 16KB

    int tid  = threadIdx.x;
    int c    = tid & 127;
    int rh   = (tid >> 7) << 4;      // 0 or 16
    int row0 = blockIdx.x * 32;

    #pragma unroll
    for (int r = 0; r < 16; r++) {
        int row = row0 + rh + r;
        float v = item_emb[(long)idx[row]*128 + c];
        e_sh[(rh + r)*128 + c] = v;
        g_e[row*128 + c] = v;
    }
    __syncthreads();

    float acc[16];

    // Q
    #pragma unroll
    for (int r = 0; r < 16; r++) acc[r] = 0.f;
    gemmT<32>(e_sh + rh*128, Wq, c, acc);
    {
        float bb = bq[c];
        #pragma unroll
        for (int r = 0; r < 16; r++) {
            float v = acc[r] + bb;
            q_sh[(rh + r)*128 + c] = v;
            g_Q[(row0 + rh + r)*128 + c] = v;
        }
    }
    // K
    #pragma unroll
    for (int r = 0; r < 16; r++) acc[r] = 0.f;
    gemmT<32>(e_sh + rh*128, Wk, c, acc);
    {
        float bb = bk[c];
        #pragma unroll
        for (int r = 0; r < 16; r++) {
            float v = acc[r] + bb;
            k_sh[(rh + r)*128 + c] = v;
            g_K[(row0 + rh + r)*128 + c] = v;
        }
    }
    __syncthreads();

    // sr[row][h] = dot(Q_h, K_h) * scale   (128 threads cover 32 rows x 4 heads)
    if (tid < 128) {
        int r = tid >> 2, h = tid & 3;
        float s = 0.f;
        #pragma unroll
        for (int d = 0; d < 32; d++)
            s = fmaf(q_sh[r*128 + h*32 + d], k_sh[r*128 + h*32 + d], s);
        g_sr[(row0 + r)*Hh + h] = s * SCALE;
    }

    // inter = e @ Wh_top + ansc[flag]   (overwrites q_sh after sr done)
    #pragma unroll
    for (int r = 0; r < 16; r++) acc[r] = 0.f;
    gemmT<32>(e_sh + rh*128, Wh, c, acc);
    __syncthreads();    // sr reads of q_sh complete
    #pragma unroll
    for (int r = 0; r < 16; r++) {
        int row = row0 + rh + r;
        q_sh[(rh + r)*128 + c] = acc[r] + g_ansc[flg[row]*128 + c];
    }
    __syncthreads();

    // V = inter @ Wv + bv
    #pragma unroll
    for (int r = 0; r < 16; r++) acc[r] = 0.f;
    gemmT<32>(q_sh + rh*128, Wv, c, acc);
    {
        float bb = bv[c];
        #pragma unroll
        for (int r = 0; r < 16; r++)
            g_V[(row0 + rh + r)*128 + c] = acc[r] + bb;
    }
}

// ---------------- kernel B: shfl-based exclusive scans ----------------
__device__ __forceinline__ float blockScanExcl(float x, int lane, int w, float* wt)
{
    float v = x;
    #pragma unroll
    for (int off = 1; off < 32; off <<= 1) {
        float t = __shfl_up_sync(0xffffffffu, v, off);
        if (lane >= off) v += t;
    }
    if (lane == 31) wt[w] = v;
    __syncthreads();
    if (w == 0) {
        float tv = wt[lane];
        #pragma unroll
        for (int off = 1; off < 32; off <<= 1) {
            float t = __shfl_up_sync(0xffffffffu, tv, off);
            if (lane >= off) tv += t;
        }
        wt[lane] = tv;
    }
    __syncthreads();
    float pre = (w > 0) ? wt[w - 1] : 0.f;
    return pre + v - x;     // exclusive prefix
}

__global__ __launch_bounds__(1024) void kB(const float* __restrict__ gaps)
{
    __shared__ float wt[32];
    int b = blockIdx.x, s = threadIdx.x;
    int lane = s & 31, w = s >> 5;

    float g = fmaxf(gaps[b*Ss + s], 1.0f);
    g_PpEx[b*Ss + s] = blockScanExcl(g, lane, w, wt);

    // exp without max-subtraction: rel = (Et-Ei)/Et is invariant to the shift
    float4 srv = *reinterpret_cast<const float4*>(&g_sr[(b*Ss + s)*4]);
    float ex[4] = { __expf(srv.x), __expf(srv.y), __expf(srv.z), __expf(srv.w) };
    #pragma unroll
    for (int h = 0; h < 4; h++) {
        __syncthreads();   // protect wt reuse
        g_EpEx[(b*Ss + s)*4 + h] = blockScanExcl(ex[h], lane, w, wt);
    }
}

// ---------------- kernel C: GEMM-tiled decayed attention, split-K over i ----
// Grid (8, NSPL, 16). 512 blocks, 4 co-resident/SM (regs capped at 64).
#define PADQ 68
#define PADP 68
__global__ __launch_bounds__(256, 4) void kC()
{
    __shared__ __align__(16) float QsT[32*PADQ];
    __shared__ __align__(16) float KsT[32*PADQ];
    __shared__ __align__(16) float Vs [64*32];
    __shared__ __align__(16) float Ps [64*PADP];
    __shared__ float Pts[64], Ets[64], iEts[64];
    __shared__ float Pis[64], Eis[64];
    __shared__ float Ls[64];

    int bh = blockIdx.z;
    int b  = bh >> 2, h = bh & 3;
    int r  = blockIdx.y;                 // split index
    int pr = blockIdx.x;                 // 0..7
    int tid = threadIdx.x;
    int tx = tid & 15, ty = tid >> 4;    // epilogue/GEMM1 mapping
    int lane = tid & 31, w = tid >> 5;   // GEMM2 mapping

    float th = g_theta[h];

    #pragma unroll 1
    for (int ph = 0; ph < 2; ph++) {
        int jt = ph ? (15 - pr) : pr;
        int t0 = 1 + jt*64;

        // stage Q tile (transposed) + per-t stats
        for (int e = tid; e < 2048; e += 256) {
            int tl = e >> 5, d = e & 31;
            int t = min(t0 + tl, Ss - 1);
            QsT[d*PADQ + tl] = g_Q[(b*Ss + t)*128 + h*32 + d];
        }
        if (tid < 64) {
            int t = min(t0 + tid, Ss - 1);
            Pts[tid] = g_PpEx[b*Ss + t];
            float Et = g_EpEx[(b*Ss + t)*Hh + h];
            Ets[tid]  = Et;
            iEts[tid] = 1.0f / Et;
        }

        float lsum[4] = {0.f, 0.f, 0.f, 0.f};
        float acc[8]  = {0.f,0.f,0.f,0.f,0.f,0.f,0.f,0.f};

        int ntile = jt + 1;
        for (int it = r; it < ntile; it += NSPL) {
            int i0 = it*64;
            __syncthreads();   // prev GEMM2 done before overwriting K/V/Ps
            // stage K (transposed), V (row-major), per-i stats
            for (int e = tid; e < 2048; e += 256) {
                int il = e >> 5, d = e & 31;
                int gi = (b*Ss + i0 + il)*128 + h*32 + d;
                KsT[d*PADQ + il] = g_K[gi];
                Vs[il*32 + d]    = g_V[gi];
            }
            if (tid < 64) {
                Pis[tid] = g_PpEx[b*Ss + i0 + tid];
                Eis[tid] = g_EpEx[(b*Ss + i0 + tid)*Hh + h];
            }
            __syncthreads();

            // ---- GEMM1: s[4][4] = Q(4t) . K(4i) over d ----
            float s00=0,s01=0,s02=0,s03=0, s10=0,s11=0,s12=0,s13=0;
            float s20=0,s21=0,s22=0,s23=0, s30=0,s31=0,s32=0,s33=0;
            #pragma unroll
            for (int d = 0; d < 32; d++) {
                float4 a = *reinterpret_cast<const float4*>(&QsT[d*PADQ + ty*4]);
                float4 k4 = *reinterpret_cast<const float4*>(&KsT[d*PADQ + tx*4]);
                s00=fmaf(a.x,k4.x,s00); s01=fmaf(a.x,k4.y,s01); s02=fmaf(a.x,k4.z,s02); s03=fmaf(a.x,k4.w,s03);
                s10=fmaf(a.y,k4.x,s10); s11=fmaf(a.y,k4.y,s11); s12=fmaf(a.y,k4.z,s12); s13=fmaf(a.y,k4.w,s13);
                s20=fmaf(a.z,k4.x,s20); s21=fmaf(a.z,k4.y,s21); s22=fmaf(a.z,k4.z,s22); s23=fmaf(a.z,k4.w,s23);
                s30=fmaf(a.w,k4.x,s30); s31=fmaf(a.w,k4.y,s31); s32=fmaf(a.w,k4.z,s32); s33=fmaf(a.w,k4.w,s33);
            }
            float sm[4][4] = {{s00,s01,s02,s03},{s10,s11,s12,s13},
                              {s20,s21,s22,s23},{s30,s31,s32,s33}};

            // ---- epilogue: decay + exp, store p ----
            float4 Pi4 = *reinterpret_cast<const float4*>(&Pis[tx*4]);
            float4 Ei4 = *reinterpret_cast<const float4*>(&Eis[tx*4]);
            float piv[4] = {Pi4.x, Pi4.y, Pi4.z, Pi4.w};
            float eiv[4] = {Ei4.x, Ei4.y, Ei4.z, Ei4.w};
            #pragma unroll
            for (int ti = 0; ti < 4; ti++) {
                int tl = ty*4 + ti;
                int t  = t0 + tl;
                float Pt = Pts[tl], Et = Ets[tl], iE = iEts[tl];
                float4 pv;
                float pout[4];
                #pragma unroll
                for (int ii = 0; ii < 4; ii++) {
                    int i = i0 + tx*4 + ii;
                    float p = 0.f;
                    if (i < t && t < Ss) {
                        float step = (float)(t - i);
                        float gd   = Pt - piv[ii];
                        float relv = (Et - eiv[ii]) * iE;
                        float pd   = step * gd * relv;
                        p = __expf(sm[ti][ii] * SCALE * __expf(-th * pd));
                    }
                    lsum[ti] += p;
                    pout[ii] = p;
                }
                pv.x = pout[0]; pv.y = pout[1]; pv.z = pout[2]; pv.w = pout[3];
                *reinterpret_cast<float4*>(&Ps[tl*PADP + tx*4]) = pv;
            }
            __syncthreads();

            // ---- GEMM2: ctx[t][d] += sum_i p[t][i] * V[i][d] ----
            #pragma unroll 4
            for (int i4 = 0; i4 < 16; i4++) {
                float v0 = Vs[(i4*4+0)*32 + lane];
                float v1 = Vs[(i4*4+1)*32 + lane];
                float v2 = Vs[(i4*4+2)*32 + lane];
                float v3 = Vs[(i4*4+3)*32 + lane];
                #pragma unroll
                for (int tt = 0; tt < 8; tt++) {
                    float4 p4 = *reinterpret_cast<const float4*>(&Ps[(w*8+tt)*PADP + i4*4]);
                    float a = acc[tt];
                    a = fmaf(p4.x, v0, a);
                    a = fmaf(p4.y, v1, a);
                    a = fmaf(p4.z, v2, a);
                    a = fmaf(p4.w, v3, a);
                    acc[tt] = a;
                }
            }
        }

        // reduce partial lsum across tx (within half-warp)
        #pragma unroll
        for (int off = 1; off < 16; off <<= 1) {
            #pragma unroll
            for (int ti = 0; ti < 4; ti++)
                lsum[ti] += __shfl_xor_sync(0xffffffffu, lsum[ti], off);
        }
        if (tx == 0) {
            #pragma unroll
            for (int ti = 0; ti < 4; ti++)
                Ls[ty*4 + ti] = lsum[ti];
        }
        __syncthreads();

        // write unnormalized partials (warp w owns t-rows w*8..w*8+7, lane = d)
        #pragma unroll
        for (int tt = 0; tt < 8; tt++) {
            int tl = w*8 + tt;
            int t  = t0 + tl;
            if (t < Ss) {
                g_pacc[r*(NROW*EMB) + (b*Ss + t)*128 + h*32 + lane] = acc[tt];
                if (lane == 0)
                    g_plsum[r*(NROW*Hh) + (b*Ss + t)*Hh + h] = Ls[tl];
            }
        }
        __syncthreads();   // before next phase restages
    }
}

// ---------------- kernel D: combine + final MLP + sigmoid + valid mask -----
__global__ __launch_bounds__(256) void kD(
    const float* __restrict__ W1, const float* __restrict__ b1,
    const float* __restrict__ W2, const float* __restrict__ b2,
    float* __restrict__ out, int npred, int out_size)
{
    __shared__ __align__(16) float f_sh[32*256];   // 32KB; reused for h after GEMM
    __shared__ float w2s[128];

    int tid  = threadIdx.x;
    int c    = tid & 127;
    int rh   = (tid >> 7) << 4;
    int row0 = blockIdx.x * 32;

    if (tid < 128) w2s[tid] = W2[tid];
    if (tid < 32) {
        int vrow = row0 + tid;
        if (vrow < Bb*Tt && Bb*Tt + vrow < out_size)
            out[Bb*Tt + vrow] = 1.0f;
    }

    // load feat = [combined ctx | e_next], combining split-K partials inline
    #pragma unroll
    for (int r = 0; r < 16; r++) {
        int rr  = rh + r;
        int row = row0 + rr;
        if (row < Bb*Tt) {
            int b  = row / Tt;
            int tt = row - b*Tt;
            int t  = tt + 1;
            int base = (b*Ss + t)*128 + c;
            int lidx = (b*Ss + t)*Hh + (c >> 5);
            float a = 0.f, l = 0.f;
            #pragma unroll
            for (int rp = 0; rp < NSPL; rp++) {
                a += g_pacc [rp*(NROW*EMB) + base];
                l += g_plsum[rp*(NROW*Hh) + lidx];
            }
            f_sh[rr*256 + c]       = a / l;
            f_sh[rr*256 + 128 + c] = g_e[base];
        } else {
            f_sh[rr*256 + c] = 0.f;
            f_sh[rr*256 + 128 + c] = 0.f;
        }
    }
    __syncthreads();

    float acc[16];
    #pragma unroll
    for (int r = 0; r < 16; r++) acc[r] = 0.f;
    gemmT<64>(f_sh + rh*256, W1, c, acc);
    float bb = b1[c];
    __syncthreads();                 // all f_sh reads complete before reuse
    #pragma unroll
    for (int r = 0; r < 16; r++)
        f_sh[(rh + r)*128 + c] = fmaxf(acc[r] + bb, 0.f);   // h overlay
    __syncthreads();

    int lane = tid & 31, w = tid >> 5;
    float b2v = b2[0];
    for (int r = w; r < 32; r += 8) {
        int row = row0 + r;
        if (row >= npred) continue;
        float s = 0.f;
        #pragma unroll
        for (int cc = lane; cc < 128; cc += 32)
            s = fmaf(f_sh[r*128 + cc], w2s[cc], s);
        #pragma unroll
        for (int off = 16; off; off >>= 1)
            s += __shfl_xor_sync(0xffffffffu, s, off);
        if (lane == 0)
            out[row] = 1.0f / (1.0f + __expf(-(s + b2v)));
    }
}

__global__ void kFill(float* out, int start, int n)
{
    int i = blockIdx.x*blockDim.x + threadIdx.x;
    if (i < n) out[start + i] = 1.0f;
}

// ---------------- launch ----------------
extern "C" void kernel_launch(void* const* d_in, const int* in_sizes, int n_in,
                              void* d_out, int out_size)
{
    const int*   idx      = (const int*)  d_in[0];
    const int*   flg      = (const int*)  d_in[1];
    const float* gaps     = (const float*)d_in[2];
    const float* item_emb = (const float*)d_in[3];
    const float* ans_emb  = (const float*)d_in[4];
    const float* Wq = (const float*)d_in[5];  const float* bq = (const float*)d_in[6];
    const float* Wk = (const float*)d_in[7];  const float* bk = (const float*)d_in[8];
    const float* Wv = (const float*)d_in[9];  const float* bv = (const float*)d_in[10];
    const float* Wh = (const float*)d_in[11]; const float* bh = (const float*)d_in[12];
    const float* W1 = (const float*)d_in[13]; const float* b1 = (const float*)d_in[14];
    const float* W2 = (const float*)d_in[15]; const float* b2 = (const float*)d_in[16];
    const float* th = (const float*)d_in[17];
    float* out = (float*)d_out;

    kP<<<1, 1024>>>(ans_emb, Wh, bh, th);
    kA<<<NROW/32, 256>>>(idx, flg, item_emb, Wq, bq, Wk, bk, Wv, bv, Wh);
    kB<<<Bb, 1024>>>(gaps);
    dim3 gC(8, NSPL, Bb*Hh);
    kC<<<gC, 256>>>();
    int npred = (out_size < Bb*Tt) ? out_size : Bb*Tt;
    kD<<<(Bb*Tt + 31)/32, 256>>>(W1, b1, W2, b2, out, npred, out_size);
    int extra = out_size - 2*Bb*Tt;
    if (extra > 0)
        kFill<<<(extra + 255)/256, 256>>>(out, 2*Bb*Tt, extra);
}

// round 10
// speedup vs baseline: 1.0924x; 1.0924x over previous
#include <cuda_runtime.h>
#include <cuda_bf16.h>
#include <math.h>

#define Bb   4
#define Ss   1024
#define EMB  128
#define Hh   4
#define Dd   32
#define Tt   (Ss-1)          // 1023
#define NROW (Bb*Ss)         // 4096
#define NSPL 3               // i-dimension split factor for kC
#define SCALE 0.17677669529663687f   // 1/sqrt(32)

// ---------------- scratch (static device allocations only) ----------------
__device__ float g_e   [NROW*EMB];
__device__ float g_Q   [NROW*EMB];
__device__ float g_K   [NROW*EMB];
__device__ float g_V   [NROW*EMB];
__device__ float g_sr  [NROW*Hh];
__device__ float g_EpEx[NROW*Hh];   // exclusive cumsum of ex, per (b,s,h)
__device__ float g_PpEx[NROW];      // exclusive cumsum of g, per (b,s)
__device__ float g_ctx [Bb*Tt*EMB];
__device__ float g_theta[Hh];
__device__ float g_ansc[2*EMB];     // ans_emb@Wh_bot + bh
__device__ float g_pacc [NSPL*NROW*EMB];   // unnormalized partial ctx
__device__ float g_plsum[NSPL*NROW*Hh];    // partial softmax denominators

// ---------------- kernel P: tiny precompute (parallel GEMV) ----------------
__global__ __launch_bounds__(1024) void kP(
    const float* __restrict__ ans_emb, const float* __restrict__ Wh,
    const float* __restrict__ bh, const float* __restrict__ traw)
{
    int tid  = threadIdx.x;      // 0..1023
    int o    = tid >> 2;         // output index 0..255  (f*128 + c)
    int part = tid & 3;          // k-segment
    int f = o >> 7, c = o & 127;
    float acc = 0.f;
    int k0 = part * 32;
    #pragma unroll 8
    for (int k = k0; k < k0 + 32; k++)
        acc = fmaf(ans_emb[f*128 + k], Wh[(128 + k)*128 + c], acc);
    acc += __shfl_xor_sync(0xffffffffu, acc, 1);
    acc += __shfl_xor_sync(0xffffffffu, acc, 2);
    if (part == 0) g_ansc[o] = acc + bh[c];
    if (tid < Hh) {
        float x = traw[tid];
        g_theta[tid] = log1pf(expf(x)) + 1e-4f;   // softplus + eps
    }
}

// ---------------- shared-mem GEMM helper: 16 rows x 128 cols ----------------
template<int KG>   // KG = K/4
__device__ __forceinline__ void gemmT(const float* Esh, const float* __restrict__ W,
                                      int c, float acc[16])
{
    const float4* e4 = reinterpret_cast<const float4*>(Esh);
    #pragma unroll 4
    for (int k4 = 0; k4 < KG; k4++) {
        const float* wp = W + (k4*4)*128 + c;
        float w0 = wp[0], w1 = wp[128], w2 = wp[256], w3 = wp[384];
        #pragma unroll
        for (int r = 0; r < 16; r++) {
            float4 ev = e4[r*KG + k4];
            acc[r] = fmaf(ev.x, w0, acc[r]);
            acc[r] = fmaf(ev.y, w1, acc[r]);
            acc[r] = fmaf(ev.z, w2, acc[r]);
            acc[r] = fmaf(ev.w, w3, acc[r]);
        }
    }
}

// ---------------- kernel A: gather + Q/K/inter/V + sr ----------------
__global__ __launch_bounds__(128) void kA(
    const int* __restrict__ idx, const int* __restrict__ flg,
    const float* __restrict__ item_emb,
    const float* __restrict__ Wq, const float* __restrict__ bq,
    const float* __restrict__ Wk, const float* __restrict__ bk,
    const float* __restrict__ Wv, const float* __restrict__ bv,
    const float* __restrict__ Wh)
{
    __shared__ __align__(16) float e_sh[16*128];
    __shared__ __align__(16) float q_sh[16*128];
    __shared__ __align__(16) float k_sh[16*128];
    __shared__ __align__(16) float i_sh[16*128];
    __shared__ int fl[16];

    int tid  = threadIdx.x;           // = output column c
    int row0 = blockIdx.x * 16;

    #pragma unroll
    for (int r = 0; r < 16; r++) {
        int row = row0 + r;
        float v = item_emb[(long)idx[row]*128 + tid];
        e_sh[r*128 + tid] = v;
        g_e[row*128 + tid] = v;
    }
    if (tid < 16) fl[tid] = flg[row0 + tid];
    __syncthreads();

    float acc[16];

    // Q
    #pragma unroll
    for (int r = 0; r < 16; r++) acc[r] = 0.f;
    gemmT<32>(e_sh, Wq, tid, acc);
    {
        float bb = bq[tid];
        #pragma unroll
        for (int r = 0; r < 16; r++) {
            float v = acc[r] + bb;
            q_sh[r*128 + tid] = v;
            g_Q[(row0 + r)*128 + tid] = v;
        }
    }
    // K
    #pragma unroll
    for (int r = 0; r < 16; r++) acc[r] = 0.f;
    gemmT<32>(e_sh, Wk, tid, acc);
    {
        float bb = bk[tid];
        #pragma unroll
        for (int r = 0; r < 16; r++) {
            float v = acc[r] + bb;
            k_sh[r*128 + tid] = v;
            g_K[(row0 + r)*128 + tid] = v;
        }
    }
    // inter = e @ Wh_top + ansc[flag]
    #pragma unroll
    for (int r = 0; r < 16; r++) acc[r] = 0.f;
    gemmT<32>(e_sh, Wh, tid, acc);
    #pragma unroll
    for (int r = 0; r < 16; r++)
        i_sh[r*128 + tid] = acc[r] + g_ansc[fl[r]*128 + tid];
    __syncthreads();

    // V = inter @ Wv + bv
    #pragma unroll
    for (int r = 0; r < 16; r++) acc[r] = 0.f;
    gemmT<32>(i_sh, Wv, tid, acc);
    {
        float bb = bv[tid];
        #pragma unroll
        for (int r = 0; r < 16; r++)
            g_V[(row0 + r)*128 + tid] = acc[r] + bb;
    }

    // sr[row][h] = dot(Q_h, K_h) * scale
    if (tid < 64) {
        int r = tid >> 2, h = tid & 3;
        float s = 0.f;
        #pragma unroll
        for (int d = 0; d < 32; d++)
            s = fmaf(q_sh[r*128 + h*32 + d], k_sh[r*128 + h*32 + d], s);
        g_sr[(row0 + r)*Hh + h] = s * SCALE;
    }
}

// ---------------- kernel B: parallel scans, one per block ----------------
// grid (5, Bb): blockIdx.x==0 -> Pp scan of gaps; 1..4 -> Ep scan for head q-1.
__device__ __forceinline__ float blockScanExcl(float x, int lane, int w, float* wt)
{
    float v = x;
    #pragma unroll
    for (int off = 1; off < 32; off <<= 1) {
        float t = __shfl_up_sync(0xffffffffu, v, off);
        if (lane >= off) v += t;
    }
    if (lane == 31) wt[w] = v;
    __syncthreads();
    if (w == 0) {
        float tv = wt[lane];
        #pragma unroll
        for (int off = 1; off < 32; off <<= 1) {
            float t = __shfl_up_sync(0xffffffffu, tv, off);
            if (lane >= off) tv += t;
        }
        wt[lane] = tv;
    }
    __syncthreads();
    float pre = (w > 0) ? wt[w - 1] : 0.f;
    return pre + v - x;     // exclusive prefix
}

__global__ __launch_bounds__(1024) void kB(const float* __restrict__ gaps)
{
    __shared__ float wt[32];
    int q = blockIdx.x;          // 0 = Pp; 1..4 = head q-1
    int b = blockIdx.y;
    int s = threadIdx.x;
    int lane = s & 31, w = s >> 5;

    float x;
    if (q == 0) x = fmaxf(gaps[b*Ss + s], 1.0f);
    else        x = __expf(g_sr[(b*Ss + s)*Hh + (q - 1)]);
    // exp without max-subtraction: rel = (Et-Ei)/Et is invariant to the shift
    float ex = blockScanExcl(x, lane, w, wt);
    if (q == 0) g_PpEx[b*Ss + s] = ex;
    else        g_EpEx[(b*Ss + s)*Hh + (q - 1)] = ex;
}

// ---------------- kernel C: GEMM-tiled decayed attention, split-K over i ----
// Grid (8, NSPL, 16). 384 blocks, 3 co-resident per SM -> one full wave.
#define PADQ 68
#define PADP 68
__global__ __launch_bounds__(256) void kC()
{
    __shared__ __align__(16) float QsT[32*PADQ];
    __shared__ __align__(16) float KsT[32*PADQ];
    __shared__ __align__(16) float Vs [64*32];
    __shared__ __align__(16) float Ps [64*PADP];
    __shared__ float Pts[64], Ets[64], iEts[64];
    __shared__ float Pis[64], Eis[64];
    __shared__ float Ls[64];

    int bh = blockIdx.z;
    int b  = bh >> 2, h = bh & 3;
    int r  = blockIdx.y;                 // split index
    int pr = blockIdx.x;                 // 0..7
    int tid = threadIdx.x;
    int tx = tid & 15, ty = tid >> 4;    // epilogue/GEMM1 mapping
    int lane = tid & 31, w = tid >> 5;   // GEMM2 mapping

    float th = g_theta[h];

    #pragma unroll 1
    for (int ph = 0; ph < 2; ph++) {
        int jt = ph ? (15 - pr) : pr;
        int t0 = 1 + jt*64;

        // stage Q tile (transposed) + per-t stats
        for (int e = tid; e < 2048; e += 256) {
            int tl = e >> 5, d = e & 31;
            int t = min(t0 + tl, Ss - 1);
            QsT[d*PADQ + tl] = g_Q[(b*Ss + t)*128 + h*32 + d];
        }
        if (tid < 64) {
            int t = min(t0 + tid, Ss - 1);
            Pts[tid] = g_PpEx[b*Ss + t];
            float Et = g_EpEx[(b*Ss + t)*Hh + h];
            Ets[tid]  = Et;
            iEts[tid] = 1.0f / Et;
        }

        float lsum[4] = {0.f, 0.f, 0.f, 0.f};
        float acc[8]  = {0.f,0.f,0.f,0.f,0.f,0.f,0.f,0.f};

        int ntile = jt + 1;
        for (int it = r; it < ntile; it += NSPL) {
            int i0 = it*64;
            __syncthreads();   // prev GEMM2 done before overwriting K/V/Ps
            // stage K (transposed), V (row-major), per-i stats
            for (int e = tid; e < 2048; e += 256) {
                int il = e >> 5, d = e & 31;
                int gi = (b*Ss + i0 + il)*128 + h*32 + d;
                KsT[d*PADQ + il] = g_K[gi];
                Vs[il*32 + d]    = g_V[gi];
            }
            if (tid < 64) {
                Pis[tid] = g_PpEx[b*Ss + i0 + tid];
                Eis[tid] = g_EpEx[(b*Ss + i0 + tid)*Hh + h];
            }
            __syncthreads();

            // ---- GEMM1: s[4][4] = Q(4t) . K(4i) over d ----
            float s00=0,s01=0,s02=0,s03=0, s10=0,s11=0,s12=0,s13=0;
            float s20=0,s21=0,s22=0,s23=0, s30=0,s31=0,s32=0,s33=0;
            #pragma unroll
            for (int d = 0; d < 32; d++) {
                float4 a = *reinterpret_cast<const float4*>(&QsT[d*PADQ + ty*4]);
                float4 k4 = *reinterpret_cast<const float4*>(&KsT[d*PADQ + tx*4]);
                s00=fmaf(a.x,k4.x,s00); s01=fmaf(a.x,k4.y,s01); s02=fmaf(a.x,k4.z,s02); s03=fmaf(a.x,k4.w,s03);
                s10=fmaf(a.y,k4.x,s10); s11=fmaf(a.y,k4.y,s11); s12=fmaf(a.y,k4.z,s12); s13=fmaf(a.y,k4.w,s13);
                s20=fmaf(a.z,k4.x,s20); s21=fmaf(a.z,k4.y,s21); s22=fmaf(a.z,k4.z,s22); s23=fmaf(a.z,k4.w,s23);
                s30=fmaf(a.w,k4.x,s30); s31=fmaf(a.w,k4.y,s31); s32=fmaf(a.w,k4.z,s32); s33=fmaf(a.w,k4.w,s33);
            }
            float sm[4][4] = {{s00,s01,s02,s03},{s10,s11,s12,s13},
                              {s20,s21,s22,s23},{s30,s31,s32,s33}};

            // ---- epilogue: decay + exp, store p ----
            float4 Pi4 = *reinterpret_cast<const float4*>(&Pis[tx*4]);
            float4 Ei4 = *reinterpret_cast<const float4*>(&Eis[tx*4]);
            float piv[4] = {Pi4.x, Pi4.y, Pi4.z, Pi4.w};
            float eiv[4] = {Ei4.x, Ei4.y, Ei4.z, Ei4.w};
            #pragma unroll
            for (int ti = 0; ti < 4; ti++) {
                int tl = ty*4 + ti;
                int t  = t0 + tl;
                float Pt = Pts[tl], Et = Ets[tl], iE = iEts[tl];
                float4 pv;
                float pout[4];
                #pragma unroll
                for (int ii = 0; ii < 4; ii++) {
                    int i = i0 + tx*4 + ii;
                    float p = 0.f;
                    if (i < t && t < Ss) {
                        float step = (float)(t - i);
                        float gd   = Pt - piv[ii];
                        float relv = (Et - eiv[ii]) * iE;
                        float pd   = step * gd * relv;
                        p = __expf(sm[ti][ii] * SCALE * __expf(-th * pd));
                    }
                    lsum[ti] += p;
                    pout[ii] = p;
                }
                pv.x = pout[0]; pv.y = pout[1]; pv.z = pout[2]; pv.w = pout[3];
                *reinterpret_cast<float4*>(&Ps[tl*PADP + tx*4]) = pv;
            }
            __syncthreads();

            // ---- GEMM2: ctx[t][d] += sum_i p[t][i] * V[i][d] ----
            #pragma unroll 4
            for (int i4 = 0; i4 < 16; i4++) {
                float v0 = Vs[(i4*4+0)*32 + lane];
                float v1 = Vs[(i4*4+1)*32 + lane];
                float v2 = Vs[(i4*4+2)*32 + lane];
                float v3 = Vs[(i4*4+3)*32 + lane];
                #pragma unroll
                for (int tt = 0; tt < 8; tt++) {
                    float4 p4 = *reinterpret_cast<const float4*>(&Ps[(w*8+tt)*PADP + i4*4]);
                    float a = acc[tt];
                    a = fmaf(p4.x, v0, a);
                    a = fmaf(p4.y, v1, a);
                    a = fmaf(p4.z, v2, a);
                    a = fmaf(p4.w, v3, a);
                    acc[tt] = a;
                }
            }
        }

        // reduce partial lsum across tx (within half-warp)
        #pragma unroll
        for (int off = 1; off < 16; off <<= 1) {
            #pragma unroll
            for (int ti = 0; ti < 4; ti++)
                lsum[ti] += __shfl_xor_sync(0xffffffffu, lsum[ti], off);
        }
        if (tx == 0) {
            #pragma unroll
            for (int ti = 0; ti < 4; ti++)
                Ls[ty*4 + ti] = lsum[ti];
        }
        __syncthreads();

        // write unnormalized partials (warp w owns t-rows w*8..w*8+7, lane = d)
        #pragma unroll
        for (int tt = 0; tt < 8; tt++) {
            int tl = w*8 + tt;
            int t  = t0 + tl;
            if (t < Ss) {
                g_pacc[r*(NROW*EMB) + (b*Ss + t)*128 + h*32 + lane] = acc[tt];
                if (lane == 0)
                    g_plsum[r*(NROW*Hh) + (b*Ss + t)*Hh + h] = Ls[tl];
            }
        }
        __syncthreads();   // before next phase restages
    }
}

// ---------------- kernel E: combine split-K partials ----------------
__global__ __launch_bounds__(256) void kE()
{
    int gid = blockIdx.x*256 + threadIdx.x;     // over Bb*Tt*EMB
    if (gid >= Bb*Tt*EMB) return;
    int c   = gid & 127;
    int row = gid >> 7;            // b*Tt + (t-1)
    int b   = row / Tt;
    int t   = row - b*Tt + 1;
    int base = (b*Ss + t)*128 + c;
    int lidx = (b*Ss + t)*Hh + (c >> 5);
    float a = 0.f, l = 0.f;
    #pragma unroll
    for (int r = 0; r < NSPL; r++) {
        a += g_pacc[r*(NROW*EMB) + base];
        l += g_plsum[r*(NROW*Hh) + lidx];
    }
    g_ctx[gid] = a / l;
}

// ---------------- kernel D: final MLP + sigmoid (+ valid-mask fill) --------
__global__ __launch_bounds__(128) void kD(
    const float* __restrict__ W1, const float* __restrict__ b1,
    const float* __restrict__ W2, const float* __restrict__ b2,
    float* __restrict__ out, int npred, int out_size)
{
    __shared__ __align__(16) float f_sh[16*256];
    __shared__ float h_sh[16*128];
    __shared__ float w2s[128];

    int tid  = threadIdx.x;
    int row0 = blockIdx.x * 16;
    w2s[tid] = W2[tid];

    // valid mask: out[Bb*Tt + row] = 1.0f (independent store, folded from kFill)
    if (tid < 16) {
        int vrow = row0 + tid;
        if (vrow < Bb*Tt && Bb*Tt + vrow < out_size)
            out[Bb*Tt + vrow] = 1.0f;
    }

    int nrows = min(16, Bb*Tt - row0);
    for (int r = 0; r < nrows; r++) {
        int row = row0 + r;
        int bb  = row / Tt;
        int tt  = row % Tt;
        f_sh[r*256 + tid]       = g_ctx[row*128 + tid];
        f_sh[r*256 + 128 + tid] = g_e[(bb*Ss + tt + 1)*128 + tid];
    }
    for (int r = nrows; r < 16; r++) {
        f_sh[r*256 + tid] = 0.f; f_sh[r*256 + 128 + tid] = 0.f;
    }
    __syncthreads();

    float acc[16];
    #pragma unroll
    for (int r = 0; r < 16; r++) acc[r] = 0.f;
    gemmT<64>(f_sh, W1, tid, acc);
    {
        float bb = b1[tid];
        #pragma unroll
        for (int r = 0; r < 16; r++)
            h_sh[r*128 + tid] = fmaxf(acc[r] + bb, 0.f);
    }
    __syncthreads();

    int lane = tid & 31, wp = tid >> 5;
    for (int r = wp; r < nrows; r += 4) {
        float s = 0.f;
        #pragma unroll
        for (int c = lane; c < 128; c += 32)
            s = fmaf(h_sh[r*128 + c], w2s[c], s);
        #pragma unroll
        for (int off = 16; off; off >>= 1)
            s += __shfl_xor_sync(0xffffffffu, s, off);
        if (lane == 0) {
            int row = row0 + r;
            if (row < npred) {
                float logit = s + b2[0];
                out[row] = 1.0f / (1.0f + __expf(-logit));
            }
        }
    }
}

__global__ void kFill(float* out, int start, int n)
{
    int i = blockIdx.x*blockDim.x + threadIdx.x;
    if (i < n) out[start + i] = 1.0f;
}

// ---------------- launch ----------------
extern "C" void kernel_launch(void* const* d_in, const int* in_sizes, int n_in,
                              void* d_out, int out_size)
{
    const int*   idx      = (const int*)  d_in[0];
    const int*   flg      = (const int*)  d_in[1];
    const float* gaps     = (const float*)d_in[2];
    const float* item_emb = (const float*)d_in[3];
    const float* ans_emb  = (const float*)d_in[4];
    const float* Wq = (const float*)d_in[5];  const float* bq = (const float*)d_in[6];
    const float* Wk = (const float*)d_in[7];  const float* bk = (const float*)d_in[8];
    const float* Wv = (const float*)d_in[9];  const float* bv = (const float*)d_in[10];
    const float* Wh = (const float*)d_in[11]; const float* bh = (const float*)d_in[12];
    const float* W1 = (const float*)d_in[13]; const float* b1 = (const float*)d_in[14];
    const float* W2 = (const float*)d_in[15]; const float* b2 = (const float*)d_in[16];
    const float* th = (const float*)d_in[17];
    float* out = (float*)d_out;

    kP<<<1, 1024>>>(ans_emb, Wh, bh, th);
    kA<<<NROW/16, 128>>>(idx, flg, item_emb, Wq, bq, Wk, bk, Wv, bv, Wh);
    dim3 gB(5, Bb);
    kB<<<gB, 1024>>>(gaps);
    dim3 gC(8, NSPL, Bb*Hh);
    kC<<<gC, 256>>>();
    kE<<<(Bb*Tt*EMB + 255)/256, 256>>>();
    int npred = (out_size < Bb*Tt) ? out_size : Bb*Tt;
    kD<<<(Bb*Tt + 15)/16, 128>>>(W1, b1, W2, b2, out, npred, out_size);
    int extra = out_size - 2*Bb*Tt;
    if (extra > 0)
        kFill<<<(extra + 255)/256, 256>>>(out, 2*Bb*Tt, extra);
}

// round 11
// speedup vs baseline: 1.1264x; 1.0311x over previous
#include <cuda_runtime.h>
#include <cuda_bf16.h>
#include <math.h>

#define Bb   4
#define Ss   1024
#define EMB  128
#define Hh   4
#define Dd   32
#define Tt   (Ss-1)          // 1023
#define NROW (Bb*Ss)         // 4096
#define NSPL 3               // i-dimension split factor for kC
#define SCALE 0.17677669529663687f   // 1/sqrt(32)
#define L2E   1.4426950408889634f
#define SCALE2 (SCALE*L2E)           // folds exp->exp2 conversion

// ---------------- scratch (static device allocations only) ----------------
__device__ float g_e   [NROW*EMB];
__device__ float g_Q   [NROW*EMB];
__device__ float g_K   [NROW*EMB];
__device__ float g_V   [NROW*EMB];
__device__ float g_sr  [NROW*Hh];
__device__ float g_EpEx[NROW*Hh];   // exclusive cumsum of ex, per (b,s,h)
__device__ float g_PpEx[NROW];      // exclusive cumsum of g, per (b,s)
__device__ float g_ctx [Bb*Tt*EMB];
__device__ float g_theta[Hh];
__device__ float g_ansc[2*EMB];     // ans_emb@Wh_bot + bh
__device__ float g_pacc [NSPL*NROW*EMB];   // unnormalized partial ctx
__device__ float g_plsum[NSPL*NROW*Hh];    // partial softmax denominators

// ---------------- fast exp2: no MUFU, pure FMA/ALU ----------------
// Input y = x*log2(e) (base-2 exponent). |err| ~1e-7 rel on valid range.
__device__ __forceinline__ float fexp2f(float y)
{
    y = fmaxf(y, -125.0f);                       // clamp: avoids exponent underflow garbage
    float z = y + 12582912.0f;                   // 1.5*2^23: round-to-nearest-int trick
    int   j = __float_as_int(z) - 0x4B400000;    // integer part
    float f = y - (z - 12582912.0f);             // fractional part in [-0.5, 0.5]
    float r = fmaf(f, 0.0013333558f, 0.0096181291f);
    r = fmaf(f, r, 0.0555041087f);
    r = fmaf(f, r, 0.2402265069f);
    r = fmaf(f, r, 0.6931471806f);
    r = fmaf(f, r, 1.0f);
    return __int_as_float(__float_as_int(r) + (j << 23));   // * 2^j
}

// ---------------- kernel P: tiny precompute (parallel GEMV) ----------------
__global__ __launch_bounds__(1024) void kP(
    const float* __restrict__ ans_emb, const float* __restrict__ Wh,
    const float* __restrict__ bh, const float* __restrict__ traw)
{
    int tid  = threadIdx.x;      // 0..1023
    int o    = tid >> 2;         // output index 0..255  (f*128 + c)
    int part = tid & 3;          // k-segment
    int f = o >> 7, c = o & 127;
    float acc = 0.f;
    int k0 = part * 32;
    #pragma unroll 8
    for (int k = k0; k < k0 + 32; k++)
        acc = fmaf(ans_emb[f*128 + k], Wh[(128 + k)*128 + c], acc);
    acc += __shfl_xor_sync(0xffffffffu, acc, 1);
    acc += __shfl_xor_sync(0xffffffffu, acc, 2);
    if (part == 0) g_ansc[o] = acc + bh[c];
    if (tid < Hh) {
        float x = traw[tid];
        g_theta[tid] = log1pf(expf(x)) + 1e-4f;   // softplus + eps
    }
}

// ---------------- shared-mem GEMM helper: 16 rows x 128 cols ----------------
template<int KG>   // KG = K/4
__device__ __forceinline__ void gemmT(const float* Esh, const float* __restrict__ W,
                                      int c, float acc[16])
{
    const float4* e4 = reinterpret_cast<const float4*>(Esh);
    #pragma unroll 4
    for (int k4 = 0; k4 < KG; k4++) {
        const float* wp = W + (k4*4)*128 + c;
        float w0 = wp[0], w1 = wp[128], w2 = wp[256], w3 = wp[384];
        #pragma unroll
        for (int r = 0; r < 16; r++) {
            float4 ev = e4[r*KG + k4];
            acc[r] = fmaf(ev.x, w0, acc[r]);
            acc[r] = fmaf(ev.y, w1, acc[r]);
            acc[r] = fmaf(ev.z, w2, acc[r]);
            acc[r] = fmaf(ev.w, w3, acc[r]);
        }
    }
}

// ---------------- kernel A: gather + Q/K/inter/V + sr ----------------
__global__ __launch_bounds__(128) void kA(
    const int* __restrict__ idx, const int* __restrict__ flg,
    const float* __restrict__ item_emb,
    const float* __restrict__ Wq, const float* __restrict__ bq,
    const float* __restrict__ Wk, const float* __restrict__ bk,
    const float* __restrict__ Wv, const float* __restrict__ bv,
    const float* __restrict__ Wh)
{
    __shared__ __align__(16) float e_sh[16*128];
    __shared__ __align__(16) float q_sh[16*128];
    __shared__ __align__(16) float k_sh[16*128];
    __shared__ __align__(16) float i_sh[16*128];
    __shared__ int fl[16];

    int tid  = threadIdx.x;           // = output column c
    int row0 = blockIdx.x * 16;

    #pragma unroll
    for (int r = 0; r < 16; r++) {
        int row = row0 + r;
        float v = item_emb[(long)idx[row]*128 + tid];
        e_sh[r*128 + tid] = v;
        g_e[row*128 + tid] = v;
    }
    if (tid < 16) fl[tid] = flg[row0 + tid];
    __syncthreads();

    float acc[16];

    // Q
    #pragma unroll
    for (int r = 0; r < 16; r++) acc[r] = 0.f;
    gemmT<32>(e_sh, Wq, tid, acc);
    {
        float bb = bq[tid];
        #pragma unroll
        for (int r = 0; r < 16; r++) {
            float v = acc[r] + bb;
            q_sh[r*128 + tid] = v;
            g_Q[(row0 + r)*128 + tid] = v;
        }
    }
    // K
    #pragma unroll
    for (int r = 0; r < 16; r++) acc[r] = 0.f;
    gemmT<32>(e_sh, Wk, tid, acc);
    {
        float bb = bk[tid];
        #pragma unroll
        for (int r = 0; r < 16; r++) {
            float v = acc[r] + bb;
            k_sh[r*128 + tid] = v;
            g_K[(row0 + r)*128 + tid] = v;
        }
    }
    // inter = e @ Wh_top + ansc[flag]
    #pragma unroll
    for (int r = 0; r < 16; r++) acc[r] = 0.f;
    gemmT<32>(e_sh, Wh, tid, acc);
    #pragma unroll
    for (int r = 0; r < 16; r++)
        i_sh[r*128 + tid] = acc[r] + g_ansc[fl[r]*128 + tid];
    __syncthreads();

    // V = inter @ Wv + bv
    #pragma unroll
    for (int r = 0; r < 16; r++) acc[r] = 0.f;
    gemmT<32>(i_sh, Wv, tid, acc);
    {
        float bb = bv[tid];
        #pragma unroll
        for (int r = 0; r < 16; r++)
            g_V[(row0 + r)*128 + tid] = acc[r] + bb;
    }

    // sr[row][h] = dot(Q_h, K_h) * scale
    if (tid < 64) {
        int r = tid >> 2, h = tid & 3;
        float s = 0.f;
        #pragma unroll
        for (int d = 0; d < 32; d++)
            s = fmaf(q_sh[r*128 + h*32 + d], k_sh[r*128 + h*32 + d], s);
        g_sr[(row0 + r)*Hh + h] = s * SCALE;
    }
}

// ---------------- kernel B: parallel scans, one per block ----------------
// grid (5, Bb): blockIdx.x==0 -> Pp scan of gaps; 1..4 -> Ep scan for head q-1.
__device__ __forceinline__ float blockScanExcl(float x, int lane, int w, float* wt)
{
    float v = x;
    #pragma unroll
    for (int off = 1; off < 32; off <<= 1) {
        float t = __shfl_up_sync(0xffffffffu, v, off);
        if (lane >= off) v += t;
    }
    if (lane == 31) wt[w] = v;
    __syncthreads();
    if (w == 0) {
        float tv = wt[lane];
        #pragma unroll
        for (int off = 1; off < 32; off <<= 1) {
            float t = __shfl_up_sync(0xffffffffu, tv, off);
            if (lane >= off) tv += t;
        }
        wt[lane] = tv;
    }
    __syncthreads();
    float pre = (w > 0) ? wt[w - 1] : 0.f;
    return pre + v - x;     // exclusive prefix
}

__global__ __launch_bounds__(1024) void kB(const float* __restrict__ gaps)
{
    __shared__ float wt[32];
    int q = blockIdx.x;          // 0 = Pp; 1..4 = head q-1
    int b = blockIdx.y;
    int s = threadIdx.x;
    int lane = s & 31, w = s >> 5;

    float x;
    if (q == 0) x = fmaxf(gaps[b*Ss + s], 1.0f);
    else        x = __expf(g_sr[(b*Ss + s)*Hh + (q - 1)]);
    // exp without max-subtraction: rel = (Et-Ei)/Et is invariant to the shift
    float ex = blockScanExcl(x, lane, w, wt);
    if (q == 0) g_PpEx[b*Ss + s] = ex;
    else        g_EpEx[(b*Ss + s)*Hh + (q - 1)] = ex;
}

// ---------------- kernel C: GEMM-tiled decayed attention, split-K over i ----
// Grid (8, NSPL, 16). 384 blocks, 3 co-resident per SM -> one full wave.
// Epilogue exponentials use fexp2f (FMA/ALU pipes) instead of MUFU __expf.
#define PADQ 68
#define PADP 68
__global__ __launch_bounds__(256) void kC()
{
    __shared__ __align__(16) float QsT[32*PADQ];
    __shared__ __align__(16) float KsT[32*PADQ];
    __shared__ __align__(16) float Vs [64*32];
    __shared__ __align__(16) float Ps [64*PADP];
    __shared__ float Pts[64], Ets[64], iEts[64];
    __shared__ float Pis[64], Eis[64];
    __shared__ float Ls[64];

    int bh = blockIdx.z;
    int b  = bh >> 2, h = bh & 3;
    int r  = blockIdx.y;                 // split index
    int pr = blockIdx.x;                 // 0..7
    int tid = threadIdx.x;
    int tx = tid & 15, ty = tid >> 4;    // epilogue/GEMM1 mapping
    int lane = tid & 31, w = tid >> 5;   // GEMM2 mapping

    float th2 = g_theta[h] * L2E;        // folds exp -> exp2

    #pragma unroll 1
    for (int ph = 0; ph < 2; ph++) {
        int jt = ph ? (15 - pr) : pr;
        int t0 = 1 + jt*64;

        // stage Q tile (transposed) + per-t stats
        for (int e = tid; e < 2048; e += 256) {
            int tl = e >> 5, d = e & 31;
            int t = min(t0 + tl, Ss - 1);
            QsT[d*PADQ + tl] = g_Q[(b*Ss + t)*128 + h*32 + d];
        }
        if (tid < 64) {
            int t = min(t0 + tid, Ss - 1);
            Pts[tid] = g_PpEx[b*Ss + t];
            float Et = g_EpEx[(b*Ss + t)*Hh + h];
            Ets[tid]  = Et;
            iEts[tid] = 1.0f / Et;
        }

        float lsum[4] = {0.f, 0.f, 0.f, 0.f};
        float acc[8]  = {0.f,0.f,0.f,0.f,0.f,0.f,0.f,0.f};

        int ntile = jt + 1;
        for (int it = r; it < ntile; it += NSPL) {
            int i0 = it*64;
            __syncthreads();   // prev GEMM2 done before overwriting K/V/Ps
            // stage K (transposed), V (row-major), per-i stats
            for (int e = tid; e < 2048; e += 256) {
                int il = e >> 5, d = e & 31;
                int gi = (b*Ss + i0 + il)*128 + h*32 + d;
                KsT[d*PADQ + il] = g_K[gi];
                Vs[il*32 + d]    = g_V[gi];
            }
            if (tid < 64) {
                Pis[tid] = g_PpEx[b*Ss + i0 + tid];
                Eis[tid] = g_EpEx[(b*Ss + i0 + tid)*Hh + h];
            }
            __syncthreads();

            // ---- GEMM1: s[4][4] = Q(4t) . K(4i) over d ----
            float s00=0,s01=0,s02=0,s03=0, s10=0,s11=0,s12=0,s13=0;
            float s20=0,s21=0,s22=0,s23=0, s30=0,s31=0,s32=0,s33=0;
            #pragma unroll
            for (int d = 0; d < 32; d++) {
                float4 a = *reinterpret_cast<const float4*>(&QsT[d*PADQ + ty*4]);
                float4 k4 = *reinterpret_cast<const float4*>(&KsT[d*PADQ + tx*4]);
                s00=fmaf(a.x,k4.x,s00); s01=fmaf(a.x,k4.y,s01); s02=fmaf(a.x,k4.z,s02); s03=fmaf(a.x,k4.w,s03);
                s10=fmaf(a.y,k4.x,s10); s11=fmaf(a.y,k4.y,s11); s12=fmaf(a.y,k4.z,s12); s13=fmaf(a.y,k4.w,s13);
                s20=fmaf(a.z,k4.x,s20); s21=fmaf(a.z,k4.y,s21); s22=fmaf(a.z,k4.z,s22); s23=fmaf(a.z,k4.w,s23);
                s30=fmaf(a.w,k4.x,s30); s31=fmaf(a.w,k4.y,s31); s32=fmaf(a.w,k4.z,s32); s33=fmaf(a.w,k4.w,s33);
            }
            float sm[4][4] = {{s00,s01,s02,s03},{s10,s11,s12,s13},
                              {s20,s21,s22,s23},{s30,s31,s32,s33}};

            // ---- epilogue: decay + exp (fexp2f), store p ----
            float4 Pi4 = *reinterpret_cast<const float4*>(&Pis[tx*4]);
            float4 Ei4 = *reinterpret_cast<const float4*>(&Eis[tx*4]);
            float piv[4] = {Pi4.x, Pi4.y, Pi4.z, Pi4.w};
            float eiv[4] = {Ei4.x, Ei4.y, Ei4.z, Ei4.w};
            #pragma unroll
            for (int ti = 0; ti < 4; ti++) {
                int tl = ty*4 + ti;
                int t  = t0 + tl;
                float Pt = Pts[tl], Et = Ets[tl], iE = iEts[tl];
                float4 pv;
                float pout[4];
                #pragma unroll
                for (int ii = 0; ii < 4; ii++) {
                    int i = i0 + tx*4 + ii;
                    float p = 0.f;
                    if (i < t && t < Ss) {
                        float step = (float)(t - i);
                        float gd   = Pt - piv[ii];
                        float relv = (Et - eiv[ii]) * iE;
                        float pd   = step * gd * relv;
                        float decay = fexp2f(-th2 * pd);           // = exp(-theta*pd)
                        p = fexp2f((sm[ti][ii] * SCALE2) * decay); // = exp(raw*decay)
                    }
                    lsum[ti] += p;
                    pout[ii] = p;
                }
                pv.x = pout[0]; pv.y = pout[1]; pv.z = pout[2]; pv.w = pout[3];
                *reinterpret_cast<float4*>(&Ps[tl*PADP + tx*4]) = pv;
            }
            __syncthreads();

            // ---- GEMM2: ctx[t][d] += sum_i p[t][i] * V[i][d] ----
            #pragma unroll 4
            for (int i4 = 0; i4 < 16; i4++) {
                float v0 = Vs[(i4*4+0)*32 + lane];
                float v1 = Vs[(i4*4+1)*32 + lane];
                float v2 = Vs[(i4*4+2)*32 + lane];
                float v3 = Vs[(i4*4+3)*32 + lane];
                #pragma unroll
                for (int tt = 0; tt < 8; tt++) {
                    float4 p4 = *reinterpret_cast<const float4*>(&Ps[(w*8+tt)*PADP + i4*4]);
                    float a = acc[tt];
                    a = fmaf(p4.x, v0, a);
                    a = fmaf(p4.y, v1, a);
                    a = fmaf(p4.z, v2, a);
                    a = fmaf(p4.w, v3, a);
                    acc[tt] = a;
                }
            }
        }

        // reduce partial lsum across tx (within half-warp)
        #pragma unroll
        for (int off = 1; off < 16; off <<= 1) {
            #pragma unroll
            for (int ti = 0; ti < 4; ti++)
                lsum[ti] += __shfl_xor_sync(0xffffffffu, lsum[ti], off);
        }
        if (tx == 0) {
            #pragma unroll
            for (int ti = 0; ti < 4; ti++)
                Ls[ty*4 + ti] = lsum[ti];
        }
        __syncthreads();

        // write unnormalized partials (warp w owns t-rows w*8..w*8+7, lane = d)
        #pragma unroll
        for (int tt = 0; tt < 8; tt++) {
            int tl = w*8 + tt;
            int t  = t0 + tl;
            if (t < Ss) {
                g_pacc[r*(NROW*EMB) + (b*Ss + t)*128 + h*32 + lane] = acc[tt];
                if (lane == 0)
                    g_plsum[r*(NROW*Hh) + (b*Ss + t)*Hh + h] = Ls[tl];
            }
        }
        __syncthreads();   // before next phase restages
    }
}

// ---------------- kernel E: combine split-K partials ----------------
__global__ __launch_bounds__(256) void kE()
{
    int gid = blockIdx.x*256 + threadIdx.x;     // over Bb*Tt*EMB
    if (gid >= Bb*Tt*EMB) return;
    int c   = gid & 127;
    int row = gid >> 7;            // b*Tt + (t-1)
    int b   = row / Tt;
    int t   = row - b*Tt + 1;
    int base = (b*Ss + t)*128 + c;
    int lidx = (b*Ss + t)*Hh + (c >> 5);
    float a = 0.f, l = 0.f;
    #pragma unroll
    for (int r = 0; r < NSPL; r++) {
        a += g_pacc[r*(NROW*EMB) + base];
        l += g_plsum[r*(NROW*Hh) + lidx];
    }
    g_ctx[gid] = a / l;
}

// ---------------- kernel D: final MLP + sigmoid (+ valid-mask fill) --------
__global__ __launch_bounds__(128) void kD(
    const float* __restrict__ W1, const float* __restrict__ b1,
    const float* __restrict__ W2, const float* __restrict__ b2,
    float* __restrict__ out, int npred, int out_size)
{
    __shared__ __align__(16) float f_sh[16*256];
    __shared__ float h_sh[16*128];
    __shared__ float w2s[128];

    int tid  = threadIdx.x;
    int row0 = blockIdx.x * 16;
    w2s[tid] = W2[tid];

    // valid mask: out[Bb*Tt + row] = 1.0f (independent store, folded from kFill)
    if (tid < 16) {
        int vrow = row0 + tid;
        if (vrow < Bb*Tt && Bb*Tt + vrow < out_size)
            out[Bb*Tt + vrow] = 1.0f;
    }

    int nrows = min(16, Bb*Tt - row0);
    for (int r = 0; r < nrows; r++) {
        int row = row0 + r;
        int bb  = row / Tt;
        int tt  = row % Tt;
        f_sh[r*256 + tid]       = g_ctx[row*128 + tid];
        f_sh[r*256 + 128 + tid] = g_e[(bb*Ss + tt + 1)*128 + tid];
    }
    for (int r = nrows; r < 16; r++) {
        f_sh[r*256 + tid] = 0.f; f_sh[r*256 + 128 + tid] = 0.f;
    }
    __syncthreads();

    float acc[16];
    #pragma unroll
    for (int r = 0; r < 16; r++) acc[r] = 0.f;
    gemmT<64>(f_sh, W1, tid, acc);
    {
        float bb = b1[tid];
        #pragma unroll
        for (int r = 0; r < 16; r++)
            h_sh[r*128 + tid] = fmaxf(acc[r] + bb, 0.f);
    }
    __syncthreads();

    int lane = tid & 31, wp = tid >> 5;
    for (int r = wp; r < nrows; r += 4) {
        float s = 0.f;
        #pragma unroll
        for (int c = lane; c < 128; c += 32)
            s = fmaf(h_sh[r*128 + c], w2s[c], s);
        #pragma unroll
        for (int off = 16; off; off >>= 1)
            s += __shfl_xor_sync(0xffffffffu, s, off);
        if (lane == 0) {
            int row = row0 + r;
            if (row < npred) {
                float logit = s + b2[0];
                out[row] = 1.0f / (1.0f + __expf(-logit));
            }
        }
    }
}

__global__ void kFill(float* out, int start, int n)
{
    int i = blockIdx.x*blockDim.x + threadIdx.x;
    if (i < n) out[start + i] = 1.0f;
}

// ---------------- launch ----------------
extern "C" void kernel_launch(void* const* d_in, const int* in_sizes, int n_in,
                              void* d_out, int out_size)
{
    const int*   idx      = (const int*)  d_in[0];
    const int*   flg      = (const int*)  d_in[1];
    const float* gaps     = (const float*)d_in[2];
    const float* item_emb = (const float*)d_in[3];
    const float* ans_emb  = (const float*)d_in[4];
    const float* Wq = (const float*)d_in[5];  const float* bq = (const float*)d_in[6];
    const float* Wk = (const float*)d_in[7];  const float* bk = (const float*)d_in[8];
    const float* Wv = (const float*)d_in[9];  const float* bv = (const float*)d_in[10];
    const float* Wh = (const float*)d_in[11]; const float* bh = (const float*)d_in[12];
    const float* W1 = (const float*)d_in[13]; const float* b1 = (const float*)d_in[14];
    const float* W2 = (const float*)d_in[15]; const float* b2 = (const float*)d_in[16];
    const float* th = (const float*)d_in[17];
    float* out = (float*)d_out;

    kP<<<1, 1024>>>(ans_emb, Wh, bh, th);
    kA<<<NROW/16, 128>>>(idx, flg, item_emb, Wq, bq, Wk, bk, Wv, bv, Wh);
    dim3 gB(5, Bb);
    kB<<<gB, 1024>>>(gaps);
    dim3 gC(8, NSPL, Bb*Hh);
    kC<<<gC, 256>>>();
    kE<<<(Bb*Tt*EMB + 255)/256, 256>>>();
    int npred = (out_size < Bb*Tt) ? out_size : Bb*Tt;
    kD<<<(Bb*Tt + 15)/16, 128>>>(W1, b1, W2, b2, out, npred, out_size);
    int extra = out_size - 2*Bb*Tt;
    if (extra > 0)
        kFill<<<(extra + 255)/256, 256>>>(out, 2*Bb*Tt, extra);
}